// round 8
// baseline (speedup 1.0000x reference)
#include <cuda_runtime.h>
#include <math.h>

typedef unsigned long long ull;

#define B      8
#define DIM    1024
#define HID    512
#define NB     16
#define SEQ    2048
#define TLEN   4096
#define NSTEPS (TLEN - SEQ)
#define NBLK   128
#define NTHR   512
#define NGRP   16            // barrier counter groups (8 blocks each)
#define GPAD   64            // 256B spacing between counters

// barrier ids
#define BAR1 0   // h1 ready
#define BAR2 1   // n_s ready
#define BAR3 2   // gelu partials ready

// smem offsets (floats)
#define OFF_W1    0        // 16384: D1 slice [8 j][2048 k]
#define OFF_W2    16384    // 8192 : D2 slice [8 i][1024 k]
#define OFF_W3    24576    // 4096 : W1 slice [4 m][1024 k]
#define OFF_WC2F  28672    // 8192 : FULL W2 [512 m][16 c]
#define OFF_RED   36864    // 1024
#define OFF_RED2  37888    // 512
#define OFF_CM1   38400    // 128   c_{s-1}+b2
#define OFF_CS    38528    // 128   c_s+b2
#define OFF_BAS   38656    // 128   basis[c][own 8 cols]
#define OFF_BD1T  38784    // 128   (basis@D1 top)[c][own 8 j]
#define OFF_BD1B  38912    // 128
#define OFF_BB    39040    // 40    biases
#define SMEM_FLOATS 39080  // ~153 KB

// ---------------- persistent state ----------------
__device__ float g_h1[B * DIM];
__device__ float g_un[2][B * DIM];          // n_s ping-pong
__device__ float g_gelu[NBLK * 32];         // per-block gelu slab (128B each)
__device__ unsigned int g_bcnt[3 * NGRP * GPAD];  // spread barrier counters
__device__ unsigned int g_done;

// ---------------- packed f32x2 FMA ----------------
__device__ __forceinline__ void fma2(ull& d, ull a, ull b) {
    asm("fma.rn.f32x2 %0, %1, %2, %0;" : "+l"(d) : "l"(a), "l"(b));
}
__device__ __forceinline__ float f2sum(ull v) {
    float lo, hi;
    asm("mov.b64 {%0,%1}, %2;" : "=f"(lo), "=f"(hi) : "l"(v));
    return lo + hi;
}

// ---------------- relaxed global loads (L2-coherent) ----------------
__device__ __forceinline__ void ldg2_rlx(ull& ax, ull& ay, const float* p) {
    asm volatile("ld.relaxed.gpu.global.v2.b64 {%0,%1}, [%2];"
                 : "=l"(ax), "=l"(ay) : "l"(p) : "memory");
}
__device__ __forceinline__ float4 ldg4_rlx(const float* p) {
    float4 v;
    asm volatile("ld.relaxed.gpu.global.v4.f32 {%0,%1,%2,%3}, [%4];"
                 : "=f"(v.x), "=f"(v.y), "=f"(v.z), "=f"(v.w) : "l"(p) : "memory");
    return v;
}
__device__ __forceinline__ float ldg_rlx(const float* p) {
    float v;
    asm volatile("ld.relaxed.gpu.global.f32 %0, [%1];" : "=f"(v) : "l"(p) : "memory");
    return v;
}

// ---------------- spread grid barrier ----------------
__device__ __forceinline__ void bar_arrive(int i) {
    asm volatile("fence.acq_rel.gpu;" ::: "memory");
    __syncthreads();
    if (threadIdx.x == 0)
        asm volatile("red.release.gpu.global.add.u32 [%0], %1;"
                     :: "l"(&g_bcnt[(i * NGRP + (blockIdx.x & (NGRP - 1))) * GPAD]),
                        "r"(1u) : "memory");
}
__device__ __forceinline__ void bar_wait(int i, unsigned tgt) {
    if (threadIdx.x < NGRP) {
        unsigned* p = &g_bcnt[(i * NGRP + threadIdx.x) * GPAD];
        unsigned v;
        do {
            asm volatile("ld.acquire.gpu.global.u32 %0, [%1];"
                         : "=r"(v) : "l"(p) : "memory");
        } while (v < tgt);
    }
    __syncthreads();
}

// ---------------- prefix copy: out[:, 0:2048, :] = x ----------------
__global__ void copy_kernel(const float4* __restrict__ x4, float4* __restrict__ out4) {
    size_t q = (size_t)blockIdx.x * blockDim.x + threadIdx.x;
    int b = (int)(q >> 19);
    size_t r = q & 524287;
    out4[((size_t)b << 20) + r] = x4[q];
}

// 8-accumulator matvec slice: acts from GLOBAL (relaxed), weights from smem.
__device__ __forceinline__ void acc8g(ull acc[8], const float* __restrict__ act_row,
                                      const float* s_w, int wstride, int woff, int kg) {
    #pragma unroll
    for (int q = 0; q < 4; ++q) {
        const int k = q * 256 + kg * 4;
        ull ax, ay;
        ldg2_rlx(ax, ay, act_row + k);
        #pragma unroll
        for (int jl = 0; jl < 8; ++jl) {
            ulonglong2 w = *reinterpret_cast<const ulonglong2*>(s_w + jl * wstride + woff + k);
            fma2(acc[jl], w.x, ax);
            fma2(acc[jl], w.y, ay);
        }
    }
}

// in-warp reduce 8 accs over kg-subgroups; lanes<8 write s_red[warp][b][8]
__device__ __forceinline__ void reduce8(float* s_red, ull acc[8], int t) {
    const int b = t & 7;
    #pragma unroll
    for (int jl = 0; jl < 8; ++jl) {
        float r = f2sum(acc[jl]);
        r += __shfl_xor_sync(0xffffffffu, r, 8);
        r += __shfl_xor_sync(0xffffffffu, r, 16);
        if ((t & 31) < 8) s_red[((t >> 5) * 8 + b) * 8 + jl] = r;
    }
}

// ---------------- persistent extrapolation kernel ----------------
__global__ void __launch_bounds__(NTHR, 1)
extrap_kernel(const float* __restrict__ x, const float* __restrict__ basis,
              const float* __restrict__ W1, const float* __restrict__ b1,
              const float* __restrict__ W2, const float* __restrict__ b2,
              const float* __restrict__ D1, const float* __restrict__ bD1,
              const float* __restrict__ D2, const float* __restrict__ bD2,
              float* __restrict__ out)
{
    extern __shared__ float sm[];
    float* s_w1   = sm + OFF_W1;
    float* s_w2   = sm + OFF_W2;
    float* s_w3   = sm + OFF_W3;
    float* s_wc2f = sm + OFF_WC2F;
    float* s_red  = sm + OFF_RED;
    float* s_red2 = sm + OFF_RED2;
    float* s_cm1  = sm + OFF_CM1;
    float* s_cs   = sm + OFF_CS;
    float* s_bas  = sm + OFF_BAS;
    float* s_bd1t = sm + OFF_BD1T;
    float* s_bd1b = sm + OFF_BD1B;
    float* s_bb   = sm + OFF_BB;

    const int bid = blockIdx.x;
    const int t   = threadIdx.x;
    const int b   = t & 7;
    const int kg  = t >> 3;                 // 0..63

    // ================= init: weights -> smem =================
    for (int idx = t; idx < 8 * 2048; idx += NTHR) {
        int jl = idx & 7, kk = idx >> 3;
        s_w1[jl * 2048 + kk] = __ldg(D1 + (size_t)kk * DIM + bid * 8 + jl);
    }
    for (int idx = t; idx < 8 * 1024; idx += NTHR) {
        int il = idx & 7, kk = idx >> 3;
        s_w2[il * 1024 + kk] = __ldg(D2 + (size_t)kk * DIM + bid * 8 + il);
    }
    for (int idx = t; idx < 4 * 1024; idx += NTHR) {
        int ml = idx & 3, kk = idx >> 2;
        s_w3[ml * 1024 + kk] = __ldg(W1 + (size_t)kk * HID + bid * 4 + ml);
    }
    for (int idx = t; idx < HID * NB; idx += NTHR) s_wc2f[idx] = __ldg(W2 + idx);
    if (t < 128) s_bas[t] = __ldg(basis + (size_t)(t >> 3) * DIM + bid * 8 + (t & 7));
    if (t >= 128 && t < 256) s_cs[t - 128] = 0.f;                    // c_{-1} = 0
    if (t >= 256 && t < 264)        s_bb[t - 256]      = __ldg(bD1 + bid * 8 + (t - 256));
    else if (t >= 264 && t < 272)   s_bb[t - 264 + 8]  = __ldg(bD2 + bid * 8 + (t - 264));
    else if (t >= 272 && t < 276)   s_bb[t - 272 + 16] = __ldg(b1 + bid * 4 + (t - 272));
    else if (t >= 276 && t < 292)   s_bb[t - 276 + 20] = __ldg(b2 + (t - 276));
    __syncthreads();

    // BD1t/BD1b = basis @ D1(top/bottom) for this block's 8 j columns
    if (t < 256) {
        int half = t >> 7, c = (t >> 3) & 15, jl = t & 7;
        const float* wr = s_w1 + jl * 2048 + half * 1024;
        const float* br = basis + (size_t)c * DIM;
        float a0 = 0.f, a1 = 0.f, a2 = 0.f, a3 = 0.f;
        for (int k = 0; k < 1024; k += 4) {
            a0 += wr[k]     * __ldg(br + k);
            a1 += wr[k + 1] * __ldg(br + k + 1);
            a2 += wr[k + 2] * __ldg(br + k + 2);
            a3 += wr[k + 3] * __ldg(br + k + 3);
        }
        (half ? s_bd1b : s_bd1t)[c * 8 + jl] = (a0 + a1) + (a2 + a3);
    }
    __syncthreads();

    // ================= preloop: h1_0 from x rows (corrections exactly 0) =================
    {
        const float* rA = x + ((size_t)b * SEQ + SEQ - 1) * DIM;   // n_{-1}
        const float* rB = x + ((size_t)b * SEQ + SEQ - 2) * DIM;   // n_{-2}
        ull acc[8];
        #pragma unroll
        for (int j = 0; j < 8; ++j) acc[j] = 0ull;
        acc8g(acc, rA, s_w1, 2048, 0,    kg);
        acc8g(acc, rB, s_w1, 2048, 1024, kg);
        reduce8(s_red, acc, t);
    }
    __syncthreads();
    if (t < 64) {
        int bb = t >> 3, jl = t & 7;
        float sum = 0.f;
        #pragma unroll
        for (int w = 0; w < 16; ++w) sum += s_red[(w * 8 + bb) * 8 + jl];
        g_h1[bb * DIM + bid * 8 + jl] = tanhf(sum + s_bb[jl]);
    }
    bar_arrive(BAR1);

    // ================= step loop =================
    for (int s = 0; s < NSTEPS; ++s) {
        const int sA = s & 1;
        const unsigned tgt = (unsigned)(s + 1) * (NBLK / NGRP);

        // ---- wait h1_s; roll coef vector ----
        bar_wait(BAR1, tgt);
        if (t < 128) s_cm1[t] = s_cs[t];          // c_{s-1}+b2 (0 at s=0)

        // ================= P2: n_s = n_{s-1} + 0.1 c_{s-1}·basis + h1_s@D2 + bD2 =================
        {
            ull acc[8];
            #pragma unroll
            for (int j = 0; j < 8; ++j) acc[j] = 0ull;
            acc8g(acc, g_h1 + b * DIM, s_w2, 1024, 0, kg);
            reduce8(s_red, acc, t);
        }
        __syncthreads();
        if (t < 64) {
            int bb = t >> 3, il = t & 7;
            int ig = bid * 8 + il;
            float sum = 0.f;
            #pragma unroll
            for (int w = 0; w < 16; ++w) sum += s_red[(w * 8 + bb) * 8 + il];
            float corr = 0.f;
            #pragma unroll
            for (int c = 0; c < NB; ++c) corr += s_cm1[bb * NB + c] * s_bas[c * 8 + il];
            float nprev = (s == 0) ? __ldg(x + ((size_t)bb * SEQ + SEQ - 1) * DIM + ig)
                                   : ldg_rlx(g_un[1 - sA] + bb * DIM + ig);
            g_un[sA][bb * DIM + ig] = nprev + 0.1f * corr + sum + s_bb[8 + il];
        }
        bar_arrive(BAR2);

        // ---- P1_{s+1} half B: n_{s-1}@D1(bottom) — old data, overlaps bar2 wakeup ----
        ull acc1[8];
        #pragma unroll
        for (int j = 0; j < 8; ++j) acc1[j] = 0ull;
        {
            const float* rB = (s == 0) ? (x + ((size_t)b * SEQ + SEQ - 1) * DIM)
                                       : (g_un[1 - sA] + b * DIM);
            acc8g(acc1, rB, s_w1, 2048, 1024, kg);
        }
        bar_wait(BAR2, tgt);

        // ================= P3: gelu partials from n_s (4 m-cols/block) -> g_gelu slab =================
        {
            const float* nrow = g_un[sA] + b * DIM;
            ull a4[4];
            #pragma unroll
            for (int m = 0; m < 4; ++m) a4[m] = 0ull;
            #pragma unroll
            for (int q = 0; q < 4; ++q) {
                const int k = q * 256 + kg * 4;
                ull ax, ay;
                ldg2_rlx(ax, ay, nrow + k);
                #pragma unroll
                for (int ml = 0; ml < 4; ++ml) {
                    ulonglong2 w = *reinterpret_cast<const ulonglong2*>(s_w3 + ml * 1024 + k);
                    fma2(a4[ml], w.x, ax);
                    fma2(a4[ml], w.y, ay);
                }
            }
            #pragma unroll
            for (int ml = 0; ml < 4; ++ml) {
                float r = f2sum(a4[ml]);
                r += __shfl_xor_sync(0xffffffffu, r, 8);
                r += __shfl_xor_sync(0xffffffffu, r, 16);
                if ((t & 31) < 8) s_red[((t >> 5) * 8 + b) * 4 + ml] = r;
            }
        }
        __syncthreads();
        if (t < 32) {
            int bb = t >> 2, ml = t & 3;
            float sum = 0.f;
            #pragma unroll
            for (int w = 0; w < 16; ++w) sum += s_red[(w * 8 + bb) * 4 + ml];
            float z = sum + s_bb[16 + ml];
            g_gelu[bid * 32 + t] = 0.5f * z * (1.0f + erff(z * 0.70710678118654752f));
        }
        bar_arrive(BAR3);

        // ---- P1_{s+1} half A: n_s@D1(top) — hides bar3 latency ----
        acc8g(acc1, g_un[sA] + b * DIM, s_w1, 2048, 0, kg);
        reduce8(s_red, acc1, t);

        bar_wait(BAR3, tgt);

        // ---- coef recompute (atomic-free): c_s = gelu @ W2, redundant per block ----
        {
            int bc = t & 127, mq = t >> 7;
            int bb = bc >> 4, cc = bc & 15;
            const float* gp = g_gelu + mq * 32 * 32 + bb * 4;
            float p = 0.f;
            #pragma unroll 4
            for (int mb = 0; mb < 32; ++mb) {
                float4 gv = ldg4_rlx(gp + mb * 32);
                int m0 = (mq * 32 + mb) * 4;
                p += gv.x * s_wc2f[(m0 + 0) * 16 + cc] + gv.y * s_wc2f[(m0 + 1) * 16 + cc]
                   + gv.z * s_wc2f[(m0 + 2) * 16 + cc] + gv.w * s_wc2f[(m0 + 3) * 16 + cc];
            }
            s_red2[t] = p;
        }
        __syncthreads();
        if (t < 128)
            s_cs[t] = (s_red2[t] + s_red2[t + 128]) + (s_red2[t + 256] + s_red2[t + 384])
                    + s_bb[20 + (t & 15)];
        __syncthreads();

        // ---- P1 tail: h1_{s+1} with folded corrections ----
        if (t < 64) {
            int bb = t >> 3, jl = t & 7;
            float sum = 0.f;
            #pragma unroll
            for (int w = 0; w < 16; ++w) sum += s_red[(w * 8 + bb) * 8 + jl];
            float cd = 0.f;
            #pragma unroll
            for (int c = 0; c < NB; ++c)
                cd += s_cs[bb * NB + c]  * s_bd1t[c * 8 + jl]
                    + s_cm1[bb * NB + c] * s_bd1b[c * 8 + jl];
            g_h1[bb * DIM + bid * 8 + jl] = tanhf(sum + 0.1f * cd + s_bb[jl]);
        }
        bar_arrive(BAR1);

        // ---- output row SEQ+s (off the critical path, after arrive) ----
        if (t >= 64 && t < 80) {
            int tt = t - 64;
            int bb = tt >> 1, hf = tt & 1;
            int c0 = bid * 8 + hf * 4;
            float4 n = ldg4_rlx(g_un[sA] + bb * DIM + c0);
            float o[4] = {n.x, n.y, n.z, n.w};
            #pragma unroll
            for (int xi = 0; xi < 4; ++xi) {
                float corr = 0.f;
                #pragma unroll
                for (int c = 0; c < NB; ++c)
                    corr += s_cs[bb * NB + c] * s_bas[c * 8 + hf * 4 + xi];
                o[xi] += 0.1f * corr;
            }
            *reinterpret_cast<float4*>(out + ((size_t)bb * TLEN + SEQ + s) * DIM + c0) =
                make_float4(o[0], o[1], o[2], o[3]);
        }
    }

    // ================= done barrier + counter reset (replay safety) =================
    __syncthreads();
    if (t == 0) {
        asm volatile("fence.acq_rel.gpu;" ::: "memory");
        asm volatile("red.release.gpu.global.add.u32 [%0], %1;"
                     :: "l"(&g_done), "r"(1u) : "memory");
        if (bid == 0) {
            unsigned v;
            do {
                asm volatile("ld.acquire.gpu.global.u32 %0, [%1];"
                             : "=r"(v) : "l"(&g_done) : "memory");
            } while (v < (unsigned)NBLK);
            for (int i = 0; i < 3 * NGRP; ++i) g_bcnt[i * GPAD] = 0;
            g_done = 0;
        }
    }
}

// ---------------- launch ----------------
extern "C" void kernel_launch(void* const* d_in, const int* in_sizes, int n_in,
                              void* d_out, int out_size) {
    const float* x     = (const float*)d_in[0];
    const float* basis = (const float*)d_in[1];
    const float* W1    = (const float*)d_in[2];
    const float* b1    = (const float*)d_in[3];
    const float* W2    = (const float*)d_in[4];
    const float* b2v   = (const float*)d_in[5];
    const float* D1    = (const float*)d_in[6];
    const float* bD1   = (const float*)d_in[7];
    const float* D2    = (const float*)d_in[8];
    const float* bD2   = (const float*)d_in[9];
    float* out = (float*)d_out;

    copy_kernel<<<4096, 1024>>>((const float4*)x, (float4*)out);

    size_t smem_bytes = (size_t)SMEM_FLOATS * sizeof(float);   // ~153 KB
    cudaFuncSetAttribute(extrap_kernel, cudaFuncAttributeMaxDynamicSharedMemorySize,
                         (int)smem_bytes);
    extrap_kernel<<<NBLK, NTHR, smem_bytes>>>(x, basis, W1, b1, W2, b2v,
                                              D1, bD1, D2, bD2, out);
}

// round 9
// speedup vs baseline: 1.3182x; 1.3182x over previous
#include <cuda_runtime.h>
#include <math.h>

typedef unsigned long long ull;

#define B      8
#define DIM    1024
#define HID    512
#define NB     16
#define SEQ    2048
#define TLEN   4096
#define NSTEPS (TLEN - SEQ)
#define NBLK   128
#define NTHR   512

// barrier ids (monotonic counter + broadcast flag)
#define BAR1 0   // h1 ready
#define BAR2 1   // n_s ready
#define BAR3 2   // coef partials ready

// smem offsets (floats)
#define OFF_W1   0        // 16384: D1 slice [8 j][2048 k]
#define OFF_W2   16384    // 8192 : D2 slice [8 i][1024 k]
#define OFF_W3   24576    // 4096 : W1 slice [4 m][1024 k]
#define OFF_RED  28672    // 1024
#define OFF_CM1  29696    // 128   c_{s-1}+b2
#define OFF_CS   29824    // 128   c_s+b2
#define OFF_BAS  29952    // 128   basis[c][own 8 cols]
#define OFF_BD1T 30080    // 128   (basis@D1 top)[c][own 8 j]
#define OFF_BD1B 30208    // 128
#define OFF_G    30336    // 32    gelu vals
#define OFF_WC2  30368    // 64    W2 slice
#define OFF_BB   30432    // 40    biases
#define SMEM_FLOATS 30472 // ~119 KB

// ---------------- persistent state ----------------
__device__ float g_h1[B * DIM];
__device__ float g_un[2][B * DIM];       // n_s ping-pong
__device__ float g_coef[2][B * NB];      // raw coef accumulators (no b2)
__device__ unsigned int g_cnt[3 * 32];   // arrival counters (128B apart)
__device__ unsigned int g_flag[3 * 32];  // broadcast flags (separate lines)
__device__ unsigned int g_done;

// ---------------- packed f32x2 FMA ----------------
__device__ __forceinline__ void fma2(ull& d, ull a, ull b) {
    asm("fma.rn.f32x2 %0, %1, %2, %0;" : "+l"(d) : "l"(a), "l"(b));
}
__device__ __forceinline__ float f2sum(ull v) {
    float lo, hi;
    asm("mov.b64 {%0,%1}, %2;" : "=f"(lo), "=f"(hi) : "l"(v));
    return lo + hi;
}

// ---------------- barrier: release-add counter, last arriver sets flag ----------------
__device__ __forceinline__ void bar_arrive(int i, unsigned tgt) {
    __syncthreads();
    if (threadIdx.x == 0) {
        unsigned old;
        asm volatile("atom.acq_rel.gpu.global.add.u32 %0, [%1], %2;"
                     : "=r"(old) : "l"(&g_cnt[i * 32]), "r"(1u) : "memory");
        if (old + 1u == tgt)
            asm volatile("st.release.gpu.global.u32 [%0], %1;"
                         :: "l"(&g_flag[i * 32]), "r"(tgt) : "memory");
    }
}
__device__ __forceinline__ void bar_wait(int i, unsigned tgt) {
    if (threadIdx.x == 0) {
        unsigned v;
        do {
            asm volatile("ld.acquire.gpu.global.u32 %0, [%1];"
                         : "=r"(v) : "l"(&g_flag[i * 32]) : "memory");
        } while (v < tgt);
    }
    __syncthreads();
}

// ---------------- prefix copy: out[:, 0:2048, :] = x ----------------
__global__ void copy_kernel(const float4* __restrict__ x4, float4* __restrict__ out4) {
    size_t q = (size_t)blockIdx.x * blockDim.x + threadIdx.x;
    int b = (int)(q >> 19);
    size_t r = q & 524287;
    out4[((size_t)b << 20) + r] = x4[q];
}

// 8-accumulator matvec slice: acts from GLOBAL (LDG), weights from smem.
__device__ __forceinline__ void acc8(ull acc[8], const float* __restrict__ act_row,
                                     const float* s_w, int wstride, int woff, int kg) {
    #pragma unroll
    for (int q = 0; q < 4; ++q) {
        const int k = q * 256 + kg * 4;
        ulonglong2 a = *reinterpret_cast<const ulonglong2*>(act_row + k);
        #pragma unroll
        for (int jl = 0; jl < 8; ++jl) {
            ulonglong2 w = *reinterpret_cast<const ulonglong2*>(s_w + jl * wstride + woff + k);
            fma2(acc[jl], w.x, a.x);
            fma2(acc[jl], w.y, a.y);
        }
    }
}

// in-warp reduce 8 accs over kg-subgroups; lanes<8 write s_red[warp][b][8]
__device__ __forceinline__ void reduce8(float* s_red, ull acc[8], int t) {
    const int b = t & 7;
    #pragma unroll
    for (int jl = 0; jl < 8; ++jl) {
        float r = f2sum(acc[jl]);
        r += __shfl_xor_sync(0xffffffffu, r, 8);
        r += __shfl_xor_sync(0xffffffffu, r, 16);
        if ((t & 31) < 8) s_red[((t >> 5) * 8 + b) * 8 + jl] = r;
    }
}

// ---------------- persistent extrapolation kernel ----------------
__global__ void __launch_bounds__(NTHR, 1)
extrap_kernel(const float* __restrict__ x, const float* __restrict__ basis,
              const float* __restrict__ W1, const float* __restrict__ b1,
              const float* __restrict__ W2, const float* __restrict__ b2,
              const float* __restrict__ D1, const float* __restrict__ bD1,
              const float* __restrict__ D2, const float* __restrict__ bD2,
              float* __restrict__ out)
{
    extern __shared__ float sm[];
    float* s_w1   = sm + OFF_W1;
    float* s_w2   = sm + OFF_W2;
    float* s_w3   = sm + OFF_W3;
    float* s_red  = sm + OFF_RED;
    float* s_cm1  = sm + OFF_CM1;
    float* s_cs   = sm + OFF_CS;
    float* s_bas  = sm + OFF_BAS;
    float* s_bd1t = sm + OFF_BD1T;
    float* s_bd1b = sm + OFF_BD1B;
    float* s_g    = sm + OFF_G;
    float* s_wc2  = sm + OFF_WC2;
    float* s_bb   = sm + OFF_BB;

    const int bid = blockIdx.x;
    const int t   = threadIdx.x;
    const int b   = t & 7;
    const int kg  = t >> 3;                 // 0..63

    // ================= init: weights -> smem =================
    for (int idx = t; idx < 8 * 2048; idx += NTHR) {
        int jl = idx & 7, kk = idx >> 3;
        s_w1[jl * 2048 + kk] = __ldg(D1 + (size_t)kk * DIM + bid * 8 + jl);
    }
    for (int idx = t; idx < 8 * 1024; idx += NTHR) {
        int il = idx & 7, kk = idx >> 3;
        s_w2[il * 1024 + kk] = __ldg(D2 + (size_t)kk * DIM + bid * 8 + il);
    }
    for (int idx = t; idx < 4 * 1024; idx += NTHR) {
        int ml = idx & 3, kk = idx >> 2;
        s_w3[ml * 1024 + kk] = __ldg(W1 + (size_t)kk * HID + bid * 4 + ml);
    }
    if (t < 128) s_bas[t] = __ldg(basis + (size_t)(t >> 3) * DIM + bid * 8 + (t & 7));
    if (t < 64)  s_wc2[t] = __ldg(W2 + (size_t)(bid * 4 + (t >> 4)) * NB + (t & 15));
    if (t >= 64 && t < 72)        s_bb[t - 64]      = __ldg(bD1 + bid * 8 + (t - 64));
    else if (t >= 72 && t < 80)   s_bb[t - 72 + 8]  = __ldg(bD2 + bid * 8 + (t - 72));
    else if (t >= 80 && t < 84)   s_bb[t - 80 + 16] = __ldg(b1 + bid * 4 + (t - 80));
    else if (t >= 84 && t < 100)  s_bb[t - 84 + 20] = __ldg(b2 + (t - 84));
    if (bid == 0 && t >= 128 && t < 256) g_coef[1][t - 128] = 0.f;   // c_{-1} = 0
    __syncthreads();

    // BD1t/BD1b = basis @ D1(top/bottom) for this block's 8 j columns
    if (t < 256) {
        int half = t >> 7, c = (t >> 3) & 15, jl = t & 7;
        const float* wr = s_w1 + jl * 2048 + half * 1024;
        const float* br = basis + (size_t)c * DIM;
        float a0 = 0.f, a1 = 0.f, a2 = 0.f, a3 = 0.f;
        for (int k = 0; k < 1024; k += 4) {
            a0 += wr[k]     * __ldg(br + k);
            a1 += wr[k + 1] * __ldg(br + k + 1);
            a2 += wr[k + 2] * __ldg(br + k + 2);
            a3 += wr[k + 3] * __ldg(br + k + 3);
        }
        (half ? s_bd1b : s_bd1t)[c * 8 + jl] = (a0 + a1) + (a2 + a3);
    }
    __syncthreads();

    // ================= preloop: h1_0 from x rows (corrections exactly 0) =================
    {
        const float* rA = x + ((size_t)b * SEQ + SEQ - 1) * DIM;   // n_{-1}
        const float* rB = x + ((size_t)b * SEQ + SEQ - 2) * DIM;   // n_{-2}
        ull acc[8];
        #pragma unroll
        for (int j = 0; j < 8; ++j) acc[j] = 0ull;
        acc8(acc, rA, s_w1, 2048, 0,    kg);
        acc8(acc, rB, s_w1, 2048, 1024, kg);
        reduce8(s_red, acc, t);
    }
    __syncthreads();
    if (t < 64) {
        int bb = t >> 3, jl = t & 7;
        float sum = 0.f;
        #pragma unroll
        for (int w = 0; w < 16; ++w) sum += s_red[(w * 8 + bb) * 8 + jl];
        g_h1[bb * DIM + bid * 8 + jl] = tanhf(sum + s_bb[jl]);
    }
    bar_arrive(BAR1, (unsigned)NBLK);

    // ================= step loop =================
    for (int s = 0; s < NSTEPS; ++s) {
        const int sA = s & 1;
        const unsigned tgt = (unsigned)(s + 1) * NBLK;

        // ---- wait h1_s; stage c_{s-1}+b2; zero c_s accumulator ----
        bar_wait(BAR1, tgt);
        if (t < 128) {
            float b2v = s_bb[20 + (t & 15)];
            s_cm1[t] = (s >= 1) ? g_coef[1 - sA][t] + b2v : 0.f;
        }
        if (bid == 0 && t >= 128 && t < 256) g_coef[sA][t - 128] = 0.f;

        // ================= P2: n_s = n_{s-1} + 0.1 c_{s-1}·basis + h1_s@D2 + bD2 =================
        {
            ull acc[8];
            #pragma unroll
            for (int j = 0; j < 8; ++j) acc[j] = 0ull;
            acc8(acc, g_h1 + b * DIM, s_w2, 1024, 0, kg);
            reduce8(s_red, acc, t);
        }
        __syncthreads();
        if (t < 64) {
            int bb = t >> 3, il = t & 7;
            int ig = bid * 8 + il;
            float sum = 0.f;
            #pragma unroll
            for (int w = 0; w < 16; ++w) sum += s_red[(w * 8 + bb) * 8 + il];
            float corr = 0.f;
            #pragma unroll
            for (int c = 0; c < NB; ++c) corr += s_cm1[bb * NB + c] * s_bas[c * 8 + il];
            float nprev = (s == 0) ? __ldg(x + ((size_t)bb * SEQ + SEQ - 1) * DIM + ig)
                                   : g_un[1 - sA][bb * DIM + ig];
            g_un[sA][bb * DIM + ig] = nprev + 0.1f * corr + sum + s_bb[8 + il];
        }
        bar_arrive(BAR2, tgt);

        // ---- P1_{s+1} half B: n_{s-1}@D1(bottom) — old data, overlaps bar2 wakeup ----
        ull acc1[8];
        #pragma unroll
        for (int j = 0; j < 8; ++j) acc1[j] = 0ull;
        {
            const float* rB = (s == 0) ? (x + ((size_t)b * SEQ + SEQ - 1) * DIM)
                                       : (g_un[1 - sA] + b * DIM);
            acc8(acc1, rB, s_w1, 2048, 1024, kg);
        }
        bar_wait(BAR2, tgt);

        // ================= P3: coef partials from n_s (4 m-cols/block) =================
        {
            const float* nrow = g_un[sA] + b * DIM;
            ull a4[4];
            #pragma unroll
            for (int m = 0; m < 4; ++m) a4[m] = 0ull;
            #pragma unroll
            for (int q = 0; q < 4; ++q) {
                const int k = q * 256 + kg * 4;
                ulonglong2 a = *reinterpret_cast<const ulonglong2*>(nrow + k);
                #pragma unroll
                for (int ml = 0; ml < 4; ++ml) {
                    ulonglong2 w = *reinterpret_cast<const ulonglong2*>(s_w3 + ml * 1024 + k);
                    fma2(a4[ml], w.x, a.x);
                    fma2(a4[ml], w.y, a.y);
                }
            }
            #pragma unroll
            for (int ml = 0; ml < 4; ++ml) {
                float r = f2sum(a4[ml]);
                r += __shfl_xor_sync(0xffffffffu, r, 8);
                r += __shfl_xor_sync(0xffffffffu, r, 16);
                if ((t & 31) < 8) s_red[((t >> 5) * 8 + b) * 4 + ml] = r;
            }
        }
        __syncthreads();
        if (t < 32) {
            int bb = t >> 2, ml = t & 3;
            float sum = 0.f;
            #pragma unroll
            for (int w = 0; w < 16; ++w) sum += s_red[(w * 8 + bb) * 4 + ml];
            float z = sum + s_bb[16 + ml];
            s_g[bb * 4 + ml] = 0.5f * z * (1.0f + erff(z * 0.70710678118654752f));
        }
        __syncthreads();
        if (t < 128) {
            int bb = t >> 4, cc = t & 15;
            float a = 0.f;
            #pragma unroll
            for (int ml = 0; ml < 4; ++ml) a += s_g[bb * 4 + ml] * s_wc2[ml * NB + cc];
            atomicAdd(&g_coef[sA][bb * NB + cc], a);
        }
        bar_arrive(BAR3, tgt);

        // ---- P1_{s+1} half A: n_s@D1(top) — hides bar3 latency ----
        acc8(acc1, g_un[sA] + b * DIM, s_w1, 2048, 0, kg);
        reduce8(s_red, acc1, t);

        bar_wait(BAR3, tgt);
        if (t < 128) s_cs[t] = g_coef[sA][t] + s_bb[20 + (t & 15)];
        __syncthreads();

        // ---- P1 tail: h1_{s+1} with folded corrections; output row SEQ+s ----
        if (t < 64) {
            int bb = t >> 3, jl = t & 7;
            float sum = 0.f;
            #pragma unroll
            for (int w = 0; w < 16; ++w) sum += s_red[(w * 8 + bb) * 8 + jl];
            float cd = 0.f;
            #pragma unroll
            for (int c = 0; c < NB; ++c)
                cd += s_cs[bb * NB + c]  * s_bd1t[c * 8 + jl]
                    + s_cm1[bb * NB + c] * s_bd1b[c * 8 + jl];
            g_h1[bb * DIM + bid * 8 + jl] = tanhf(sum + 0.1f * cd + s_bb[jl]);
        }
        if (t >= 64 && t < 80) {
            int tt = t - 64;
            int bb = tt >> 1, hf = tt & 1;
            int c0 = bid * 8 + hf * 4;
            float4 n = *reinterpret_cast<const float4*>(g_un[sA] + bb * DIM + c0);
            float o[4] = {n.x, n.y, n.z, n.w};
            #pragma unroll
            for (int xi = 0; xi < 4; ++xi) {
                float corr = 0.f;
                #pragma unroll
                for (int c = 0; c < NB; ++c)
                    corr += s_cs[bb * NB + c] * s_bas[c * 8 + hf * 4 + xi];
                o[xi] += 0.1f * corr;
            }
            *reinterpret_cast<float4*>(out + ((size_t)bb * TLEN + SEQ + s) * DIM + c0) =
                make_float4(o[0], o[1], o[2], o[3]);
        }
        bar_arrive(BAR1, tgt + NBLK);
    }

    // ================= done barrier + counter reset (replay safety) =================
    __syncthreads();
    if (t == 0) {
        unsigned old;
        asm volatile("atom.acq_rel.gpu.global.add.u32 %0, [%1], %2;"
                     : "=r"(old) : "l"(&g_done), "r"(1u) : "memory");
        if (bid == 0) {
            unsigned v;
            do {
                asm volatile("ld.acquire.gpu.global.u32 %0, [%1];"
                             : "=r"(v) : "l"(&g_done) : "memory");
            } while (v < (unsigned)NBLK);
            #pragma unroll
            for (int i = 0; i < 3; ++i) { g_cnt[i * 32] = 0; g_flag[i * 32] = 0; }
            g_done = 0;
        }
    }
}

// ---------------- launch ----------------
extern "C" void kernel_launch(void* const* d_in, const int* in_sizes, int n_in,
                              void* d_out, int out_size) {
    const float* x     = (const float*)d_in[0];
    const float* basis = (const float*)d_in[1];
    const float* W1    = (const float*)d_in[2];
    const float* b1    = (const float*)d_in[3];
    const float* W2    = (const float*)d_in[4];
    const float* b2v   = (const float*)d_in[5];
    const float* D1    = (const float*)d_in[6];
    const float* bD1   = (const float*)d_in[7];
    const float* D2    = (const float*)d_in[8];
    const float* bD2   = (const float*)d_in[9];
    float* out = (float*)d_out;

    copy_kernel<<<4096, 1024>>>((const float4*)x, (float4*)out);

    size_t smem_bytes = (size_t)SMEM_FLOATS * sizeof(float);   // ~119 KB
    cudaFuncSetAttribute(extrap_kernel, cudaFuncAttributeMaxDynamicSharedMemorySize,
                         (int)smem_bytes);
    extrap_kernel<<<NBLK, NTHR, smem_bytes>>>(x, basis, W1, b1, W2, b2v,
                                              D1, bD1, D2, bD2, out);
}

// round 10
// speedup vs baseline: 1.4828x; 1.1248x over previous
#include <cuda_runtime.h>
#include <math.h>

typedef unsigned long long ull;

#define B      8
#define DIM    1024
#define HID    512
#define NB     16
#define SEQ    2048
#define TLEN   4096
#define NSTEPS (TLEN - SEQ)
#define NBLK   128
#define NTHR   512
#define NGRP   16            // barrier counter groups (8 blocks each)
#define GPAD   32            // 128B spacing
#define NREP   8             // coef accumulator replicas

// barrier ids
#define BAR1 0   // h1 ready
#define BAR2 1   // n_s ready
#define BAR3 2   // coef partials ready

// smem offsets (floats)
#define OFF_W1   0        // 16384: D1 slice [8 j][2048 k]
#define OFF_W2   16384    // 8192 : D2 slice [8 i][1024 k]
#define OFF_W3   24576    // 4096 : W1 slice [4 m][1024 k]
#define OFF_RED  28672    // 1024
#define OFF_CM1  29696    // 128   c_{s-1}+b2
#define OFF_CS   29824    // 128   c_s+b2
#define OFF_BAS  29952    // 128   basis[c][own 8 cols]
#define OFF_BD1T 30080    // 128   (basis@D1 top)[c][own 8 j]
#define OFF_BD1B 30208    // 128
#define OFF_G    30336    // 32    gelu vals
#define OFF_WC2  30368    // 64    W2 slice
#define OFF_BB   30432    // 40    biases
#define SMEM_FLOATS 30472 // ~119 KB

// ---------------- persistent state ----------------
__device__ float g_h1[B * DIM];
__device__ float g_un[2][B * DIM];          // n_s ping-pong
__device__ float g_coefR[2][NREP][B * NB];  // replicated coef accumulators
__device__ unsigned int g_bcnt[3 * NGRP * GPAD];  // spread barrier counters
__device__ unsigned int g_done;

// ---------------- packed f32x2 FMA ----------------
__device__ __forceinline__ void fma2(ull& d, ull a, ull b) {
    asm("fma.rn.f32x2 %0, %1, %2, %0;" : "+l"(d) : "l"(a), "l"(b));
}
__device__ __forceinline__ float f2sum(ull v) {
    float lo, hi;
    asm("mov.b64 {%0,%1}, %2;" : "=f"(lo), "=f"(hi) : "l"(v));
    return lo + hi;
}

// ---------------- spread grid barrier (R6 semantics, 16-way counters) ----------------
__device__ __forceinline__ void bar_arrive(int i) {
    __syncthreads();
    if (threadIdx.x == 0)
        asm volatile("red.release.gpu.global.add.u32 [%0], %1;"
                     :: "l"(&g_bcnt[(i * NGRP + (blockIdx.x & (NGRP - 1))) * GPAD]),
                        "r"(1u) : "memory");
}
__device__ __forceinline__ void bar_wait(int i, unsigned tgt) {   // tgt = (s+1)*8
    if (threadIdx.x < NGRP) {
        const unsigned* p = &g_bcnt[(i * NGRP + threadIdx.x) * GPAD];
        unsigned v;
        do {
            asm volatile("ld.acquire.gpu.global.u32 %0, [%1];"
                         : "=r"(v) : "l"(p) : "memory");
        } while (v < tgt);
    }
    __syncthreads();
}

// ---------------- prefix copy: out[:, 0:2048, :] = x ----------------
__global__ void copy_kernel(const float4* __restrict__ x4, float4* __restrict__ out4) {
    size_t q = (size_t)blockIdx.x * blockDim.x + threadIdx.x;
    int b = (int)(q >> 19);
    size_t r = q & 524287;
    out4[((size_t)b << 20) + r] = x4[q];
}

// 8-accumulator matvec slice: acts from GLOBAL (LDG), weights from smem.
__device__ __forceinline__ void acc8(ull acc[8], const float* __restrict__ act_row,
                                     const float* s_w, int wstride, int woff, int kg) {
    #pragma unroll
    for (int q = 0; q < 4; ++q) {
        const int k = q * 256 + kg * 4;
        ulonglong2 a = *reinterpret_cast<const ulonglong2*>(act_row + k);
        #pragma unroll
        for (int jl = 0; jl < 8; ++jl) {
            ulonglong2 w = *reinterpret_cast<const ulonglong2*>(s_w + jl * wstride + woff + k);
            fma2(acc[jl], w.x, a.x);
            fma2(acc[jl], w.y, a.y);
        }
    }
}

// in-warp reduce 8 accs over kg-subgroups; lanes<8 write s_red[warp][b][8]
__device__ __forceinline__ void reduce8(float* s_red, ull acc[8], int t) {
    const int b = t & 7;
    #pragma unroll
    for (int jl = 0; jl < 8; ++jl) {
        float r = f2sum(acc[jl]);
        r += __shfl_xor_sync(0xffffffffu, r, 8);
        r += __shfl_xor_sync(0xffffffffu, r, 16);
        if ((t & 31) < 8) s_red[((t >> 5) * 8 + b) * 8 + jl] = r;
    }
}

// ---------------- persistent extrapolation kernel ----------------
__global__ void __launch_bounds__(NTHR, 1)
extrap_kernel(const float* __restrict__ x, const float* __restrict__ basis,
              const float* __restrict__ W1, const float* __restrict__ b1,
              const float* __restrict__ W2, const float* __restrict__ b2,
              const float* __restrict__ D1, const float* __restrict__ bD1,
              const float* __restrict__ D2, const float* __restrict__ bD2,
              float* __restrict__ out)
{
    extern __shared__ float sm[];
    float* s_w1   = sm + OFF_W1;
    float* s_w2   = sm + OFF_W2;
    float* s_w3   = sm + OFF_W3;
    float* s_red  = sm + OFF_RED;
    float* s_cm1  = sm + OFF_CM1;
    float* s_cs   = sm + OFF_CS;
    float* s_bas  = sm + OFF_BAS;
    float* s_bd1t = sm + OFF_BD1T;
    float* s_bd1b = sm + OFF_BD1B;
    float* s_g    = sm + OFF_G;
    float* s_wc2  = sm + OFF_WC2;
    float* s_bb   = sm + OFF_BB;

    const int bid = blockIdx.x;
    const int t   = threadIdx.x;
    const int b   = t & 7;
    const int kg  = t >> 3;                 // 0..63

    // ================= init: weights -> smem =================
    for (int idx = t; idx < 8 * 2048; idx += NTHR) {
        int jl = idx & 7, kk = idx >> 3;
        s_w1[jl * 2048 + kk] = __ldg(D1 + (size_t)kk * DIM + bid * 8 + jl);
    }
    for (int idx = t; idx < 8 * 1024; idx += NTHR) {
        int il = idx & 7, kk = idx >> 3;
        s_w2[il * 1024 + kk] = __ldg(D2 + (size_t)kk * DIM + bid * 8 + il);
    }
    for (int idx = t; idx < 4 * 1024; idx += NTHR) {
        int ml = idx & 3, kk = idx >> 2;
        s_w3[ml * 1024 + kk] = __ldg(W1 + (size_t)kk * HID + bid * 4 + ml);
    }
    if (t < 128) s_bas[t] = __ldg(basis + (size_t)(t >> 3) * DIM + bid * 8 + (t & 7));
    if (t < 64)  s_wc2[t] = __ldg(W2 + (size_t)(bid * 4 + (t >> 4)) * NB + (t & 15));
    if (t >= 64 && t < 72)        s_bb[t - 64]      = __ldg(bD1 + bid * 8 + (t - 64));
    else if (t >= 72 && t < 80)   s_bb[t - 72 + 8]  = __ldg(bD2 + bid * 8 + (t - 72));
    else if (t >= 80 && t < 84)   s_bb[t - 80 + 16] = __ldg(b1 + bid * 4 + (t - 80));
    else if (t >= 84 && t < 100)  s_bb[t - 84 + 20] = __ldg(b2 + (t - 84));
    if (t >= 128 && t < 256) s_cs[t - 128] = 0.f;   // c_{-1}+b2 == 0 path (b2 is zeros-agnostic: c_{-1} term unused at s=0)
    __syncthreads();

    // BD1t/BD1b = basis @ D1(top/bottom) for this block's 8 j columns
    if (t < 256) {
        int half = t >> 7, c = (t >> 3) & 15, jl = t & 7;
        const float* wr = s_w1 + jl * 2048 + half * 1024;
        const float* br = basis + (size_t)c * DIM;
        float a0 = 0.f, a1 = 0.f, a2 = 0.f, a3 = 0.f;
        for (int k = 0; k < 1024; k += 4) {
            a0 += wr[k]     * __ldg(br + k);
            a1 += wr[k + 1] * __ldg(br + k + 1);
            a2 += wr[k + 2] * __ldg(br + k + 2);
            a3 += wr[k + 3] * __ldg(br + k + 3);
        }
        (half ? s_bd1b : s_bd1t)[c * 8 + jl] = (a0 + a1) + (a2 + a3);
    }
    __syncthreads();

    // ================= preloop: h1_0 from x rows (corrections exactly 0) =================
    {
        const float* rA = x + ((size_t)b * SEQ + SEQ - 1) * DIM;   // n_{-1}
        const float* rB = x + ((size_t)b * SEQ + SEQ - 2) * DIM;   // n_{-2}
        ull acc[8];
        #pragma unroll
        for (int j = 0; j < 8; ++j) acc[j] = 0ull;
        acc8(acc, rA, s_w1, 2048, 0,    kg);
        acc8(acc, rB, s_w1, 2048, 1024, kg);
        reduce8(s_red, acc, t);
    }
    __syncthreads();
    if (t < 64) {
        int bb = t >> 3, jl = t & 7;
        float sum = 0.f;
        #pragma unroll
        for (int w = 0; w < 16; ++w) sum += s_red[(w * 8 + bb) * 8 + jl];
        g_h1[bb * DIM + bid * 8 + jl] = tanhf(sum + s_bb[jl]);
    }
    bar_arrive(BAR1);

    // ================= step loop =================
    for (int s = 0; s < NSTEPS; ++s) {
        const int sA = s & 1;
        const unsigned tgt = (unsigned)(s + 1) * (NBLK / NGRP);

        // ---- wait h1_s; roll c_{s-1}+b2 from smem; blocks 0-7 zero this step's replicas ----
        bar_wait(BAR1, tgt);
        if (t < 128) s_cm1[t] = s_cs[t];
        if (bid < NREP && t >= 128 && t < 256)
            g_coefR[sA][bid][t - 128] = 0.f;

        // ================= P2: n_s = n_{s-1} + 0.1 c_{s-1}·basis + h1_s@D2 + bD2 =================
        {
            ull acc[8];
            #pragma unroll
            for (int j = 0; j < 8; ++j) acc[j] = 0ull;
            acc8(acc, g_h1 + b * DIM, s_w2, 1024, 0, kg);
            reduce8(s_red, acc, t);
        }
        __syncthreads();
        if (t < 64) {
            int bb = t >> 3, il = t & 7;
            int ig = bid * 8 + il;
            float sum = 0.f;
            #pragma unroll
            for (int w = 0; w < 16; ++w) sum += s_red[(w * 8 + bb) * 8 + il];
            float corr = 0.f;
            #pragma unroll
            for (int c = 0; c < NB; ++c) corr += s_cm1[bb * NB + c] * s_bas[c * 8 + il];
            float nprev = (s == 0) ? __ldg(x + ((size_t)bb * SEQ + SEQ - 1) * DIM + ig)
                                   : g_un[1 - sA][bb * DIM + ig];
            g_un[sA][bb * DIM + ig] = nprev + 0.1f * corr + sum + s_bb[8 + il];
        }
        bar_arrive(BAR2);

        // ---- P1_{s+1} half B: n_{s-1}@D1(bottom) — old data, overlaps bar2 wakeup ----
        ull acc1[8];
        #pragma unroll
        for (int j = 0; j < 8; ++j) acc1[j] = 0ull;
        {
            const float* rB = (s == 0) ? (x + ((size_t)b * SEQ + SEQ - 1) * DIM)
                                       : (g_un[1 - sA] + b * DIM);
            acc8(acc1, rB, s_w1, 2048, 1024, kg);
        }
        bar_wait(BAR2, tgt);

        // ================= P3: coef partials from n_s (4 m-cols/block) =================
        {
            const float* nrow = g_un[sA] + b * DIM;
            ull a4[4];
            #pragma unroll
            for (int m = 0; m < 4; ++m) a4[m] = 0ull;
            #pragma unroll
            for (int q = 0; q < 4; ++q) {
                const int k = q * 256 + kg * 4;
                ulonglong2 a = *reinterpret_cast<const ulonglong2*>(nrow + k);
                #pragma unroll
                for (int ml = 0; ml < 4; ++ml) {
                    ulonglong2 w = *reinterpret_cast<const ulonglong2*>(s_w3 + ml * 1024 + k);
                    fma2(a4[ml], w.x, a.x);
                    fma2(a4[ml], w.y, a.y);
                }
            }
            #pragma unroll
            for (int ml = 0; ml < 4; ++ml) {
                float r = f2sum(a4[ml]);
                r += __shfl_xor_sync(0xffffffffu, r, 8);
                r += __shfl_xor_sync(0xffffffffu, r, 16);
                if ((t & 31) < 8) s_red[((t >> 5) * 8 + b) * 4 + ml] = r;
            }
        }
        __syncthreads();
        if (t < 32) {
            int bb = t >> 2, ml = t & 3;
            float sum = 0.f;
            #pragma unroll
            for (int w = 0; w < 16; ++w) sum += s_red[(w * 8 + bb) * 4 + ml];
            float z = sum + s_bb[16 + ml];
            s_g[bb * 4 + ml] = 0.5f * z * (1.0f + erff(z * 0.70710678118654752f));
        }
        __syncthreads();
        if (t < 128) {
            int bb = t >> 4, cc = t & 15;
            float a = 0.f;
            #pragma unroll
            for (int ml = 0; ml < 4; ++ml) a += s_g[bb * 4 + ml] * s_wc2[ml * NB + cc];
            atomicAdd(&g_coefR[sA][bid & (NREP - 1)][bb * NB + cc], a);
        }
        bar_arrive(BAR3);

        // ---- P1_{s+1} half A: n_s@D1(top) — hides bar3 latency ----
        acc8(acc1, g_un[sA] + b * DIM, s_w1, 2048, 0, kg);
        reduce8(s_red, acc1, t);

        bar_wait(BAR3, tgt);
        if (t < 128) {
            float c = s_bb[20 + (t & 15)];
            #pragma unroll
            for (int r = 0; r < NREP; ++r) c += g_coefR[sA][r][t];
            s_cs[t] = c;
        }
        __syncthreads();

        // ---- P1 tail: h1_{s+1} with folded corrections; output row SEQ+s ----
        if (t < 64) {
            int bb = t >> 3, jl = t & 7;
            float sum = 0.f;
            #pragma unroll
            for (int w = 0; w < 16; ++w) sum += s_red[(w * 8 + bb) * 8 + jl];
            float cd = 0.f;
            #pragma unroll
            for (int c = 0; c < NB; ++c)
                cd += s_cs[bb * NB + c]  * s_bd1t[c * 8 + jl]
                    + s_cm1[bb * NB + c] * s_bd1b[c * 8 + jl];
            g_h1[bb * DIM + bid * 8 + jl] = tanhf(sum + 0.1f * cd + s_bb[jl]);
        }
        if (t >= 64 && t < 80) {
            int tt = t - 64;
            int bb = tt >> 1, hf = tt & 1;
            int c0 = bid * 8 + hf * 4;
            float4 n = *reinterpret_cast<const float4*>(g_un[sA] + bb * DIM + c0);
            float o[4] = {n.x, n.y, n.z, n.w};
            #pragma unroll
            for (int xi = 0; xi < 4; ++xi) {
                float corr = 0.f;
                #pragma unroll
                for (int c = 0; c < NB; ++c)
                    corr += s_cs[bb * NB + c] * s_bas[c * 8 + hf * 4 + xi];
                o[xi] += 0.1f * corr;
            }
            *reinterpret_cast<float4*>(out + ((size_t)bb * TLEN + SEQ + s) * DIM + c0) =
                make_float4(o[0], o[1], o[2], o[3]);
        }
        bar_arrive(BAR1);
    }

    // ================= done barrier + counter reset (replay safety) =================
    __syncthreads();
    if (t == 0) {
        asm volatile("red.release.gpu.global.add.u32 [%0], %1;"
                     :: "l"(&g_done), "r"(1u) : "memory");
        if (bid == 0) {
            unsigned v;
            do {
                asm volatile("ld.acquire.gpu.global.u32 %0, [%1];"
                             : "=r"(v) : "l"(&g_done) : "memory");
            } while (v < (unsigned)NBLK);
            for (int i = 0; i < 3 * NGRP; ++i) g_bcnt[i * GPAD] = 0;
            g_done = 0;
        }
    }
}

// ---------------- launch ----------------
extern "C" void kernel_launch(void* const* d_in, const int* in_sizes, int n_in,
                              void* d_out, int out_size) {
    const float* x     = (const float*)d_in[0];
    const float* basis = (const float*)d_in[1];
    const float* W1    = (const float*)d_in[2];
    const float* b1    = (const float*)d_in[3];
    const float* W2    = (const float*)d_in[4];
    const float* b2v   = (const float*)d_in[5];
    const float* D1    = (const float*)d_in[6];
    const float* bD1   = (const float*)d_in[7];
    const float* D2    = (const float*)d_in[8];
    const float* bD2   = (const float*)d_in[9];
    float* out = (float*)d_out;

    copy_kernel<<<4096, 1024>>>((const float4*)x, (float4*)out);

    size_t smem_bytes = (size_t)SMEM_FLOATS * sizeof(float);   // ~119 KB
    cudaFuncSetAttribute(extrap_kernel, cudaFuncAttributeMaxDynamicSharedMemorySize,
                         (int)smem_bytes);
    extrap_kernel<<<NBLK, NTHR, smem_bytes>>>(x, basis, W1, b1, W2, b2v,
                                              D1, bD1, D2, bD2, out);
}

// round 11
// speedup vs baseline: 1.8238x; 1.2300x over previous
#include <cuda_runtime.h>
#include <math.h>

typedef unsigned long long ull;

#define B      8
#define DIM    1024
#define HID    512
#define NB     16
#define SEQ    2048
#define TLEN   4096
#define NSTEPS (TLEN - SEQ)
#define NBLK   128
#define NTHR   512
#define NGRP   16
#define GPAD   32
#define NREP   8

#define BAR1 0   // h1 ready
#define BAR2 1   // n_s + coef partials ready

// smem offsets (floats)
#define OFF_W1    0        // 16384: D1 slice [8 j][2048 k]
#define OFF_W2    16384    // 8192 : D2 col slice [8 i][1024 k]
#define OFF_E     24576    // 4096 : E=D2@W1 slice [4 m][1024 i]
#define OFF_RED   28672    // 1536 : [(w*8+b)*12]
#define OFF_C     30208    // 256  : s_c[2][128] coef+b2 ping-pong
#define OFF_BAS   30464    // 128
#define OFF_BD1T  30592    // 128
#define OFF_BD1B  30720    // 128
#define OFF_BASW1 30848    // 64   : (basis@W1)[c][4 m]
#define OFF_G     30912    // 32
#define OFF_WC2   30944    // 64
#define OFF_NOWN  31008    // 64   : own n cols [8 b][8 il]
#define OFF_Z     31072    // 32   : own z [8 b][4 ml]
#define OFF_BB    31104    // 40   : bD1own8,bD2own8,b1own4(unused),b2@20..35,zb@36..39
#define SMEM_FLOATS 31144  // ~121.7 KB

// ---------------- persistent state ----------------
__device__ float g_h1[B * DIM];
__device__ float g_un[2][B * DIM];
__device__ float g_coefR[2][NREP][B * NB];
__device__ unsigned int g_bcnt[2 * NGRP * GPAD];
__device__ unsigned int g_done;

// ---------------- packed f32x2 FMA ----------------
__device__ __forceinline__ void fma2(ull& d, ull a, ull b) {
    asm("fma.rn.f32x2 %0, %1, %2, %0;" : "+l"(d) : "l"(a), "l"(b));
}
__device__ __forceinline__ float f2sum(ull v) {
    float lo, hi;
    asm("mov.b64 {%0,%1}, %2;" : "=f"(lo), "=f"(hi) : "l"(v));
    return lo + hi;
}

// ---------------- grid barrier (R10 style) ----------------
__device__ __forceinline__ void bar_arrive(int i) {
    __syncthreads();
    if (threadIdx.x == 0)
        asm volatile("red.release.gpu.global.add.u32 [%0], %1;"
                     :: "l"(&g_bcnt[(i * NGRP + (blockIdx.x & (NGRP - 1))) * GPAD]),
                        "r"(1u) : "memory");
}
__device__ __forceinline__ void bar_wait(int i, unsigned tgt) {
    if (threadIdx.x < NGRP) {
        const unsigned* p = &g_bcnt[(i * NGRP + threadIdx.x) * GPAD];
        unsigned v;
        do {
            asm volatile("ld.acquire.gpu.global.u32 %0, [%1];"
                         : "=r"(v) : "l"(p) : "memory");
        } while (v < tgt);
    }
    __syncthreads();
}

// ---------------- prefix copy ----------------
__global__ void copy_kernel(const float4* __restrict__ x4, float4* __restrict__ out4) {
    size_t q = (size_t)blockIdx.x * blockDim.x + threadIdx.x;
    int b = (int)(q >> 19);
    size_t r = q & 524287;
    out4[((size_t)b << 20) + r] = x4[q];
}

__device__ __forceinline__ void acc8(ull acc[8], const float* __restrict__ act_row,
                                     const float* s_w, int wstride, int woff, int kg) {
    #pragma unroll
    for (int q = 0; q < 4; ++q) {
        const int k = q * 256 + kg * 4;
        ulonglong2 a = *reinterpret_cast<const ulonglong2*>(act_row + k);
        #pragma unroll
        for (int jl = 0; jl < 8; ++jl) {
            ulonglong2 w = *reinterpret_cast<const ulonglong2*>(s_w + jl * wstride + woff + k);
            fma2(acc[jl], w.x, a.x);
            fma2(acc[jl], w.y, a.y);
        }
    }
}

template <int N>
__device__ __forceinline__ void reduceN(float* s_red, ull* acc, int t) {
    const int b = t & 7;
    #pragma unroll
    for (int o = 0; o < N; ++o) {
        float r = f2sum(acc[o]);
        r += __shfl_xor_sync(0xffffffffu, r, 8);
        r += __shfl_xor_sync(0xffffffffu, r, 16);
        if ((t & 31) < 8) s_red[((t >> 5) * 8 + b) * N + o] = r;
    }
}

// ---------------- persistent extrapolation kernel ----------------
__global__ void __launch_bounds__(NTHR, 1)
extrap_kernel(const float* __restrict__ x, const float* __restrict__ basis,
              const float* __restrict__ W1, const float* __restrict__ b1,
              const float* __restrict__ W2, const float* __restrict__ b2,
              const float* __restrict__ D1, const float* __restrict__ bD1,
              const float* __restrict__ D2, const float* __restrict__ bD2,
              float* __restrict__ out)
{
    extern __shared__ float sm[];
    float* s_w1    = sm + OFF_W1;
    float* s_w2    = sm + OFF_W2;
    float* s_E     = sm + OFF_E;
    float* s_red   = sm + OFF_RED;
    float* s_c     = sm + OFF_C;
    float* s_bas   = sm + OFF_BAS;
    float* s_bd1t  = sm + OFF_BD1T;
    float* s_bd1b  = sm + OFF_BD1B;
    float* s_basW1 = sm + OFF_BASW1;
    float* s_g     = sm + OFF_G;
    float* s_wc2   = sm + OFF_WC2;
    float* s_nown  = sm + OFF_NOWN;
    float* s_z     = sm + OFF_Z;
    float* s_bb    = sm + OFF_BB;

    const int bid = blockIdx.x;
    const int t   = threadIdx.x;
    const int b   = t & 7;
    const int kg  = t >> 3;

    // ===== init stage 1: W1 own 4 cols -> s_w1 (temp) =====
    for (int idx = t; idx < 4 * 1024; idx += NTHR) {
        int ml = idx & 3, kk = idx >> 2;
        s_w1[ml * 1024 + kk] = __ldg(W1 + (size_t)kk * HID + bid * 4 + ml);
    }
    __syncthreads();

    // ===== init stage 2: E[ml][i] = sum_k D2[i,k] * W1[k, own ml] (warp-coop per i) =====
    {
        const int wrp = t >> 5, lane = t & 31;
        for (int i = wrp; i < DIM; i += 16) {
            const float4* drow = reinterpret_cast<const float4*>(D2 + (size_t)i * DIM);
            ull a0 = 0, a1 = 0, a2 = 0, a3 = 0;
            #pragma unroll
            for (int kc = 0; kc < 8; ++kc) {
                int k4 = kc * 32 + lane;
                float4 d = __ldg(drow + k4);
                ull dx, dy;
                asm("mov.b64 %0, {%1,%2};" : "=l"(dx) : "f"(d.x), "f"(d.y));
                asm("mov.b64 %0, {%1,%2};" : "=l"(dy) : "f"(d.z), "f"(d.w));
                const float* wb = s_w1 + k4 * 4;
                ulonglong2 w0 = *reinterpret_cast<const ulonglong2*>(wb);
                fma2(a0, w0.x, dx); fma2(a0, w0.y, dy);
                ulonglong2 w1v = *reinterpret_cast<const ulonglong2*>(wb + 1024);
                fma2(a1, w1v.x, dx); fma2(a1, w1v.y, dy);
                ulonglong2 w2v = *reinterpret_cast<const ulonglong2*>(wb + 2048);
                fma2(a2, w2v.x, dx); fma2(a2, w2v.y, dy);
                ulonglong2 w3v = *reinterpret_cast<const ulonglong2*>(wb + 3072);
                fma2(a3, w3v.x, dx); fma2(a3, w3v.y, dy);
            }
            float r0 = f2sum(a0), r1 = f2sum(a1), r2 = f2sum(a2), r3 = f2sum(a3);
            #pragma unroll
            for (int off = 16; off; off >>= 1) {
                r0 += __shfl_xor_sync(0xffffffffu, r0, off);
                r1 += __shfl_xor_sync(0xffffffffu, r1, off);
                r2 += __shfl_xor_sync(0xffffffffu, r2, off);
                r3 += __shfl_xor_sync(0xffffffffu, r3, off);
            }
            if (lane == 0) {
                s_E[i] = r0; s_E[1024 + i] = r1; s_E[2048 + i] = r2; s_E[3072 + i] = r3;
            }
        }
    }
    __syncthreads();

    // ===== init stage 3: small dots using W1 temp =====
    if (t < 32) {          // z_{-1} init: (bb=t>>2, ml=t&3)
        const float4* xr = reinterpret_cast<const float4*>(x + ((size_t)(t >> 2) * SEQ + SEQ - 1) * DIM);
        const float* wml = s_w1 + (t & 3) * 1024;
        float acc = 0.f;
        for (int k4 = 0; k4 < 256; ++k4) {
            float4 xv = __ldg(xr + k4);
            const float* w = wml + k4 * 4;
            acc += xv.x * w[0] + xv.y * w[1] + xv.z * w[2] + xv.w * w[3];
        }
        s_z[t] = acc + __ldg(b1 + bid * 4 + (t & 3));
    } else if (t < 96) {   // basW1: (c=(t-32)>>2, ml=(t-32)&3)
        int tt = t - 32;
        const float4* br = reinterpret_cast<const float4*>(basis + (size_t)(tt >> 2) * DIM);
        const float* wml = s_w1 + (tt & 3) * 1024;
        float acc = 0.f;
        for (int k4 = 0; k4 < 256; ++k4) {
            float4 bv = __ldg(br + k4);
            const float* w = wml + k4 * 4;
            acc += bv.x * w[0] + bv.y * w[1] + bv.z * w[2] + bv.w * w[3];
        }
        s_basW1[tt] = acc;
    } else if (t < 100) {  // zb[ml] = bD2 @ W1col
        const float4* bd = reinterpret_cast<const float4*>(bD2);
        const float* wml = s_w1 + (t - 96) * 1024;
        float acc = 0.f;
        for (int k4 = 0; k4 < 256; ++k4) {
            float4 bv = __ldg(bd + k4);
            const float* w = wml + k4 * 4;
            acc += bv.x * w[0] + bv.y * w[1] + bv.z * w[2] + bv.w * w[3];
        }
        s_bb[36 + (t - 96)] = acc;
    }
    __syncthreads();

    // ===== init stage 4: main weight slices + small state =====
    for (int idx = t; idx < 8 * 2048; idx += NTHR) {
        int jl = idx & 7, kk = idx >> 3;
        s_w1[jl * 2048 + kk] = __ldg(D1 + (size_t)kk * DIM + bid * 8 + jl);
    }
    for (int idx = t; idx < 8 * 1024; idx += NTHR) {
        int il = idx & 7, kk = idx >> 3;
        s_w2[il * 1024 + kk] = __ldg(D2 + (size_t)kk * DIM + bid * 8 + il);
    }
    if (t < 128) s_bas[t] = __ldg(basis + (size_t)(t >> 3) * DIM + bid * 8 + (t & 7));
    if (t < 256) s_c[t] = 0.f;                        // c_{-1}=0 (and c_0 slot, overwritten)
    if (t >= 128 && t < 192) {                        // n_{-1} own cols
        int tt = t - 128;
        s_nown[tt] = __ldg(x + ((size_t)(tt >> 3) * SEQ + SEQ - 1) * DIM + bid * 8 + (tt & 7));
    }
    if (t >= 192 && t < 256) {                        // W2 slice
        int tt = t - 192;
        s_wc2[tt] = __ldg(W2 + (size_t)(bid * 4 + (tt >> 4)) * NB + (tt & 15));
    }
    if (t >= 256 && t < 264)       s_bb[t - 256]      = __ldg(bD1 + bid * 8 + (t - 256));
    else if (t >= 264 && t < 272)  s_bb[t - 264 + 8]  = __ldg(bD2 + bid * 8 + (t - 264));
    else if (t >= 272 && t < 288)  s_bb[20 + t - 272] = __ldg(b2 + (t - 272));
    if (bid < NREP && t < 256) g_coefR[t >> 7][bid][t & 127] = 0.f;
    __syncthreads();

    // ===== init stage 5: BD1t/BD1b = basis @ D1(top/bottom) own 8 j cols =====
    if (t < 256) {
        int half = t >> 7, c = (t >> 3) & 15, jl = t & 7;
        const float* wr = s_w1 + jl * 2048 + half * 1024;
        const float* br = basis + (size_t)c * DIM;
        float a0 = 0.f, a1 = 0.f, a2 = 0.f, a3 = 0.f;
        for (int k = 0; k < 1024; k += 4) {
            a0 += wr[k]     * __ldg(br + k);
            a1 += wr[k + 1] * __ldg(br + k + 1);
            a2 += wr[k + 2] * __ldg(br + k + 2);
            a3 += wr[k + 3] * __ldg(br + k + 3);
        }
        (half ? s_bd1b : s_bd1t)[c * 8 + jl] = (a0 + a1) + (a2 + a3);
    }
    __syncthreads();

    // ===== preloop: h1_0 = tanh(x_{-1}@D1t + x_{-2}@D1b + bD1) =====
    {
        const float* rA = x + ((size_t)b * SEQ + SEQ - 1) * DIM;
        const float* rB = x + ((size_t)b * SEQ + SEQ - 2) * DIM;
        ull acc[8];
        #pragma unroll
        for (int j = 0; j < 8; ++j) acc[j] = 0ull;
        acc8(acc, rA, s_w1, 2048, 0,    kg);
        acc8(acc, rB, s_w1, 2048, 1024, kg);
        reduceN<8>(s_red, acc, t);
    }
    __syncthreads();
    if (t < 64) {
        int bb = t >> 3, jl = t & 7;
        float sum = 0.f;
        #pragma unroll
        for (int w = 0; w < 16; ++w) sum += s_red[(w * 8 + bb) * 8 + jl];
        g_h1[bb * DIM + bid * 8 + jl] = tanhf(sum + s_bb[jl]);
    }
    bar_arrive(BAR1);

    // ================= step loop (2 barriers/step) =================
    for (int s = 0; s < NSTEPS; ++s) {
        const int p = s & 1;
        const unsigned tgt = (unsigned)(s + 1) * (NBLK / NGRP);
        const float* cm1 = s_c + (1 - p) * 128;        // c_{s-1}+b2

        bar_wait(BAR1, tgt);
        if (bid < NREP && t >= 128 && t < 256) g_coefR[1 - p][bid][t - 128] = 0.f;

        // ---- segA: combined matvec over h1_s: 8 n-cols (D2 slice) + 4 z-cols (E slice) ----
        {
            ull acc[12];
            #pragma unroll
            for (int o = 0; o < 12; ++o) acc[o] = 0ull;
            const float* h1row = g_h1 + b * DIM;
            #pragma unroll
            for (int q = 0; q < 4; ++q) {
                const int k = q * 256 + kg * 4;
                ulonglong2 a = *reinterpret_cast<const ulonglong2*>(h1row + k);
                #pragma unroll
                for (int jl = 0; jl < 8; ++jl) {
                    ulonglong2 w = *reinterpret_cast<const ulonglong2*>(s_w2 + jl * 1024 + k);
                    fma2(acc[jl], w.x, a.x);
                    fma2(acc[jl], w.y, a.y);
                }
                #pragma unroll
                for (int ml = 0; ml < 4; ++ml) {
                    ulonglong2 w = *reinterpret_cast<const ulonglong2*>(s_E + ml * 1024 + k);
                    fma2(acc[8 + ml], w.x, a.x);
                    fma2(acc[8 + ml], w.y, a.y);
                }
            }
            reduceN<12>(s_red, acc, t);
        }
        __syncthreads();
        if (t < 64) {                                  // n-col tail
            int bb = t >> 3, il = t & 7;
            float sum = 0.f;
            #pragma unroll
            for (int w = 0; w < 16; ++w) sum += s_red[(w * 8 + bb) * 12 + il];
            float corr = 0.f;
            #pragma unroll
            for (int c = 0; c < NB; ++c) corr += cm1[bb * NB + c] * s_bas[c * 8 + il];
            float nv = s_nown[t] + 0.1f * corr + sum + s_bb[8 + il];
            s_nown[t] = nv;
            g_un[p][bb * DIM + bid * 8 + il] = nv;
        } else if (t < 96) {                           // z tail + gelu
            int tt = t - 64, bb = tt >> 2, ml = tt & 3;
            float sum = 0.f;
            #pragma unroll
            for (int w = 0; w < 16; ++w) sum += s_red[(w * 8 + bb) * 12 + 8 + ml];
            float zc = 0.f;
            #pragma unroll
            for (int c = 0; c < NB; ++c) zc += cm1[bb * NB + c] * s_basW1[c * 4 + ml];
            float z = s_z[tt] + sum + 0.1f * zc + s_bb[36 + ml];
            s_z[tt] = z;
            s_g[tt] = 0.5f * z * (1.0f + erff(z * 0.70710678118654752f));
        }
        __syncthreads();
        if (t < 128) {                                 // coef partials
            int bb = t >> 4, cc = t & 15;
            float a = 0.f;
            #pragma unroll
            for (int ml = 0; ml < 4; ++ml) a += s_g[bb * 4 + ml] * s_wc2[ml * NB + cc];
            atomicAdd(&g_coefR[p][bid & (NREP - 1)][t], a);
        }
        bar_arrive(BAR2);

        // ---- P1 halfB: n_{s-1}@D1(bottom) — old data, hides BAR2 ----
        ull acc1[8];
        #pragma unroll
        for (int o = 0; o < 8; ++o) acc1[o] = 0ull;
        {
            const float* rB = (s == 0) ? (x + ((size_t)b * SEQ + SEQ - 1) * DIM)
                                       : (g_un[1 - p] + b * DIM);
            acc8(acc1, rB, s_w1, 2048, 1024, kg);
        }
        bar_wait(BAR2, tgt);

        // ---- segB: coef replica sum (loads overlap halfA) + P1 halfA ----
        float crep = 0.f;
        if (t < 128) {
            #pragma unroll
            for (int r = 0; r < NREP; ++r) crep += g_coefR[p][r][t];
        }
        acc8(acc1, g_un[p] + b * DIM, s_w1, 2048, 0, kg);
        reduceN<8>(s_red, acc1, t);
        if (t < 128) s_c[p * 128 + t] = crep + s_bb[20 + (t & 15)];
        __syncthreads();
        if (t < 64) {                                  // h1_{s+1} tail
            int bb = t >> 3, jl = t & 7;
            float sum = 0.f;
            #pragma unroll
            for (int w = 0; w < 16; ++w) sum += s_red[(w * 8 + bb) * 8 + jl];
            float cd = 0.f;
            #pragma unroll
            for (int c = 0; c < NB; ++c)
                cd += s_c[p * 128 + bb * NB + c] * s_bd1t[c * 8 + jl]
                    + cm1[bb * NB + c]           * s_bd1b[c * 8 + jl];
            g_h1[bb * DIM + bid * 8 + jl] = tanhf(sum + 0.1f * cd + s_bb[jl]);
        }
        bar_arrive(BAR1);

        // ---- output row SEQ+s (after arrive; hides next BAR1 wait) ----
        if (t >= 64 && t < 80) {
            int tt = t - 64, bb = tt >> 1, hf = tt & 1;
            int c0 = bid * 8 + hf * 4;
            float o[4];
            #pragma unroll
            for (int xi = 0; xi < 4; ++xi) {
                float corr = 0.f;
                #pragma unroll
                for (int c = 0; c < NB; ++c)
                    corr += s_c[p * 128 + bb * NB + c] * s_bas[c * 8 + hf * 4 + xi];
                o[xi] = s_nown[bb * 8 + hf * 4 + xi] + 0.1f * corr;
            }
            *reinterpret_cast<float4*>(out + ((size_t)bb * TLEN + SEQ + s) * DIM + c0) =
                make_float4(o[0], o[1], o[2], o[3]);
        }
    }

    // ================= done barrier + counter reset (replay safety) =================
    __syncthreads();
    if (t == 0) {
        asm volatile("red.release.gpu.global.add.u32 [%0], %1;"
                     :: "l"(&g_done), "r"(1u) : "memory");
        if (bid == 0) {
            unsigned v;
            do {
                asm volatile("ld.acquire.gpu.global.u32 %0, [%1];"
                             : "=r"(v) : "l"(&g_done) : "memory");
            } while (v < (unsigned)NBLK);
            for (int i = 0; i < 2 * NGRP; ++i) g_bcnt[i * GPAD] = 0;
            g_done = 0;
        }
    }
}

// ---------------- launch ----------------
extern "C" void kernel_launch(void* const* d_in, const int* in_sizes, int n_in,
                              void* d_out, int out_size) {
    const float* x     = (const float*)d_in[0];
    const float* basis = (const float*)d_in[1];
    const float* W1    = (const float*)d_in[2];
    const float* b1    = (const float*)d_in[3];
    const float* W2    = (const float*)d_in[4];
    const float* b2v   = (const float*)d_in[5];
    const float* D1    = (const float*)d_in[6];
    const float* bD1   = (const float*)d_in[7];
    const float* D2    = (const float*)d_in[8];
    const float* bD2   = (const float*)d_in[9];
    float* out = (float*)d_out;

    copy_kernel<<<4096, 1024>>>((const float4*)x, (float4*)out);

    size_t smem_bytes = (size_t)SMEM_FLOATS * sizeof(float);   // ~121.7 KB
    cudaFuncSetAttribute(extrap_kernel, cudaFuncAttributeMaxDynamicSharedMemorySize,
                         (int)smem_bytes);
    extrap_kernel<<<NBLK, NTHR, smem_bytes>>>(x, basis, W1, b1, W2, b2v,
                                              D1, bD1, D2, bD2, out);
}

// round 12
// speedup vs baseline: 1.9876x; 1.0898x over previous
#include <cuda_runtime.h>
#include <math.h>

typedef unsigned long long ull;

#define B      8
#define DIM    1024
#define HID    512
#define NB     16
#define SEQ    2048
#define TLEN   4096
#define NSTEPS (TLEN - SEQ)
#define NBLK   128
#define NTHR   512
#define NGRP   16
#define GPAD   32
#define NREP   8

#define BAR1 0   // h1 ready
#define BAR2 1   // coef partials ready

// smem offsets (floats)
#define OFF_D1    0        // 16384: D1 own [8jl][2048] (init only)
#define OFF_G     16384    // 16384: Gt/Gb own [8jl][2048] (first 1024 = Gt)
#define OFF_W2    32768    // 8192 : D2 own [8il][1024]; W1own temp [4][1024] during init
#define OFF_E     40960    // 4096 : E=D2@W1 own [4ml][1024]
#define OFF_RED   45056    // 3584
#define OFF_C     48640    // 256  : s_c[2][128] coef+b2 ping-pong
#define OFF_BAS   48896    // 128
#define OFF_BD1T  49024    // 128
#define OFF_BD1B  49152    // 128
#define OFF_BASW1 49280    // 64
#define OFF_G8    49344    // 32   gelu vals
#define OFF_WC2   49376    // 64
#define OFF_NOWN  49440    // 64
#define OFF_Z     49504    // 32
#define OFF_WP    49536    // 64
#define OFF_VP    49600    // 64
#define OFF_BB    49664    // 64: bD1[0..7] bD2[8..15] b2[20..35] zb[36..39] bD2D1t[40..47] bD2D1b[48..55]
#define SMEM_FLOATS 49728  // ~194 KB

// ---------------- persistent state ----------------
__device__ float g_h1[2][B * DIM];               // ping-pong h1
__device__ float g_coefR[2][NREP][B * NB];
__device__ unsigned int g_bcnt[2 * NGRP * GPAD];
__device__ unsigned int g_done;

// ---------------- packed f32x2 FMA ----------------
__device__ __forceinline__ void fma2(ull& d, ull a, ull b) {
    asm("fma.rn.f32x2 %0, %1, %2, %0;" : "+l"(d) : "l"(a), "l"(b));
}
__device__ __forceinline__ float f2sum(ull v) {
    float lo, hi;
    asm("mov.b64 {%0,%1}, %2;" : "=f"(lo), "=f"(hi) : "l"(v));
    return lo + hi;
}

// ---------------- spread grid barrier ----------------
__device__ __forceinline__ void bar_arrive(int i) {
    __syncthreads();
    if (threadIdx.x == 0)
        asm volatile("red.release.gpu.global.add.u32 [%0], %1;"
                     :: "l"(&g_bcnt[(i * NGRP + (blockIdx.x & (NGRP - 1))) * GPAD]),
                        "r"(1u) : "memory");
}
__device__ __forceinline__ void bar_wait(int i, unsigned tgt) {
    if (threadIdx.x < NGRP) {
        const unsigned* p = &g_bcnt[(i * NGRP + threadIdx.x) * GPAD];
        unsigned v;
        do {
            asm volatile("ld.acquire.gpu.global.u32 %0, [%1];"
                         : "=r"(v) : "l"(p) : "memory");
        } while (v < tgt);
    }
    __syncthreads();
}

// ---------------- prefix copy ----------------
__global__ void copy_kernel(const float4* __restrict__ x4, float4* __restrict__ out4) {
    size_t q = (size_t)blockIdx.x * blockDim.x + threadIdx.x;
    int b = (int)(q >> 19);
    size_t r = q & 524287;
    out4[((size_t)b << 20) + r] = x4[q];
}

// matvec slice: acts from GLOBAL, weights from smem; 8 accumulators
__device__ __forceinline__ void acc8(ull acc[8], const float* __restrict__ act_row,
                                     const float* s_w, int wstride, int woff, int kg) {
    #pragma unroll
    for (int q = 0; q < 4; ++q) {
        const int k = q * 256 + kg * 4;
        ulonglong2 a = *reinterpret_cast<const ulonglong2*>(act_row + k);
        #pragma unroll
        for (int jl = 0; jl < 8; ++jl) {
            ulonglong2 w = *reinterpret_cast<const ulonglong2*>(s_w + jl * wstride + woff + k);
            fma2(acc[jl], w.x, a.x);
            fma2(acc[jl], w.y, a.y);
        }
    }
}

template <int N>
__device__ __forceinline__ void reduceN(float* red_base, ull* acc, int t) {
    const int b = t & 7;
    #pragma unroll
    for (int o = 0; o < N; ++o) {
        float r = f2sum(acc[o]);
        r += __shfl_xor_sync(0xffffffffu, r, 8);
        r += __shfl_xor_sync(0xffffffffu, r, 16);
        if ((t & 31) < 8) red_base[((t >> 5) * 8 + b) * N + o] = r;
    }
}

// 1024-length dot: global float4 stream vs smem column
__device__ __forceinline__ float dot1024(const float* __restrict__ gsrc, const float* scol) {
    const float4* g4 = reinterpret_cast<const float4*>(gsrc);
    float a0 = 0.f, a1 = 0.f, a2 = 0.f, a3 = 0.f;
    for (int k4 = 0; k4 < 256; ++k4) {
        float4 v = __ldg(g4 + k4);
        const float* w = scol + k4 * 4;
        a0 += v.x * w[0]; a1 += v.y * w[1]; a2 += v.z * w[2]; a3 += v.w * w[3];
    }
    return (a0 + a1) + (a2 + a3);
}

// ---------------- persistent extrapolation kernel ----------------
__global__ void __launch_bounds__(NTHR, 1)
extrap_kernel(const float* __restrict__ x, const float* __restrict__ basis,
              const float* __restrict__ W1, const float* __restrict__ b1,
              const float* __restrict__ W2, const float* __restrict__ b2,
              const float* __restrict__ D1, const float* __restrict__ bD1,
              const float* __restrict__ D2, const float* __restrict__ bD2,
              float* __restrict__ out)
{
    extern __shared__ float sm[];
    float* s_D1    = sm + OFF_D1;
    float* s_G     = sm + OFF_G;
    float* s_w2    = sm + OFF_W2;     // W1own temp during init, then D2own
    float* s_E     = sm + OFF_E;
    float* s_red   = sm + OFF_RED;
    float* s_c     = sm + OFF_C;
    float* s_bas   = sm + OFF_BAS;
    float* s_bd1t  = sm + OFF_BD1T;
    float* s_bd1b  = sm + OFF_BD1B;
    float* s_basW1 = sm + OFF_BASW1;
    float* s_g8    = sm + OFF_G8;
    float* s_wc2   = sm + OFF_WC2;
    float* s_nown  = sm + OFF_NOWN;
    float* s_z     = sm + OFF_Z;
    float* s_wp    = sm + OFF_WP;
    float* s_vp    = sm + OFF_VP;
    float* s_bb    = sm + OFF_BB;

    const int bid = blockIdx.x;
    const int t   = threadIdx.x;
    const int b   = t & 7;
    const int kg  = t >> 3;

    // ===== stage 1: loads =====
    for (int idx = t; idx < 8 * 2048; idx += NTHR) {
        int jl = idx & 7, kk = idx >> 3;
        s_D1[jl * 2048 + kk] = __ldg(D1 + (size_t)kk * DIM + bid * 8 + jl);
    }
    for (int idx = t; idx < 4 * 1024; idx += NTHR) {   // W1 own temp
        int ml = idx & 3, kk = idx >> 2;
        s_w2[ml * 1024 + kk] = __ldg(W1 + (size_t)kk * HID + bid * 4 + ml);
    }
    if (t < 128) s_bas[t] = __ldg(basis + (size_t)(t >> 3) * DIM + bid * 8 + (t & 7));
    else if (t < 192) {                                 // n_{-1} own cols
        int tt = t - 128;
        s_nown[tt] = __ldg(x + ((size_t)(tt >> 3) * SEQ + SEQ - 1) * DIM + bid * 8 + (tt & 7));
    } else if (t < 256) {                               // W2 slice
        int tt = t - 192;
        s_wc2[tt] = __ldg(W2 + (size_t)(bid * 4 + (tt >> 4)) * NB + (tt & 15));
    } else if (t < 264)  s_bb[t - 256]      = __ldg(bD1 + bid * 8 + (t - 256));
    else if (t < 272)    s_bb[t - 264 + 8]  = __ldg(bD2 + bid * 8 + (t - 264));
    else if (t < 288)    s_bb[20 + t - 272] = __ldg(b2 + (t - 272));
    for (int idx = t; idx < 256; idx += NTHR) s_c[idx] = 0.f;
    if (bid < NREP) for (int idx = t; idx < 256; idx += NTHR) g_coefR[idx >> 7][bid][idx & 127] = 0.f;
    __syncthreads();

    // ===== stage 2a: big small-dots =====
    if (t < 256) {                   // BD1t/BD1b
        int half = t >> 7, c = (t >> 3) & 15, jl = t & 7;
        float v = dot1024(basis + (size_t)c * DIM, s_D1 + jl * 2048 + half * 1024);
        (half ? s_bd1b : s_bd1t)[c * 8 + jl] = v;
    } else if (t < 320) {            // basW1
        int tt = t - 256;
        s_basW1[tt] = dot1024(basis + (size_t)(tt >> 2) * DIM, s_w2 + (tt & 3) * 1024);
    } else if (t < 384) {            // wp = x_{-1}@D1t own
        int tt = t - 320;
        s_wp[tt] = dot1024(x + ((size_t)(tt >> 3) * SEQ + SEQ - 1) * DIM,
                           s_D1 + (tt & 7) * 2048);
    } else if (t < 448) {            // vp = x_{-1}@D1b own
        int tt = t - 384;
        s_vp[tt] = dot1024(x + ((size_t)(tt >> 3) * SEQ + SEQ - 1) * DIM,
                           s_D1 + (tt & 7) * 2048 + 1024);
    } else {                         // vp2 = x_{-2}@D1b own -> s_red temp
        int tt = t - 448;
        s_red[tt] = dot1024(x + ((size_t)(tt >> 3) * SEQ + SEQ - 2) * DIM,
                            s_D1 + (tt & 7) * 2048 + 1024);
    }
    __syncthreads();

    // ===== stage 2b: tiny dots + h1_0 =====
    if (t < 32) {                    // z_{-1} init
        float v = dot1024(x + ((size_t)(t >> 2) * SEQ + SEQ - 1) * DIM, s_w2 + (t & 3) * 1024);
        s_z[t] = v + __ldg(b1 + bid * 4 + (t & 3));
    } else if (t < 36) {             // zb = bD2@W1own
        s_bb[36 + (t - 32)] = dot1024(bD2, s_w2 + (t - 32) * 1024);
    } else if (t < 44) {             // bD2@D1t own
        s_bb[40 + (t - 36)] = dot1024(bD2, s_D1 + (t - 36) * 2048);
    } else if (t < 52) {             // bD2@D1b own
        s_bb[48 + (t - 44)] = dot1024(bD2, s_D1 + (t - 44) * 2048 + 1024);
    } else if (t >= 64 && t < 128) { // h1_0 = tanh(wp_{-1} + vp_{-2} + bD1)
        int tt = t - 64;
        g_h1[0][(tt >> 3) * DIM + bid * 8 + (tt & 7)] =
            tanhf(s_wp[tt] + s_red[tt] + s_bb[tt & 7]);
    }
    __syncthreads();

    // ===== stage 3: Gt/Gb/E = D2 @ [D1t | D1b | W1] own cols (warp-coop, KT=4, OT=5) =====
    {
        const int wrp = t >> 5, lane = t & 31;
        for (int g = 0; g < 16; ++g) {
            const int k0 = (wrp * 16 + g) * 4;
            #pragma unroll
            for (int os = 0; os < 4; ++os) {
                float acc[20];
                #pragma unroll
                for (int q = 0; q < 20; ++q) acc[q] = 0.f;
                for (int c8 = 0; c8 < 8; ++c8) {
                    const int i4 = c8 * 32 + lane;
                    float4 wv[5];
                    #pragma unroll
                    for (int c = 0; c < 5; ++c) {
                        const int o = os * 5 + c;
                        const float* wptr = (o < 8)
                            ? (s_D1 + o * 2048 + i4 * 4)
                            : (o < 16 ? (s_D1 + (o - 8) * 2048 + 1024 + i4 * 4)
                                      : (s_w2 + (o - 16) * 1024 + i4 * 4));
                        wv[c] = *reinterpret_cast<const float4*>(wptr);
                    }
                    #pragma unroll
                    for (int r = 0; r < 4; ++r) {
                        float4 d = __ldg(reinterpret_cast<const float4*>(
                                             D2 + (size_t)(k0 + r) * DIM) + i4);
                        #pragma unroll
                        for (int c = 0; c < 5; ++c)
                            acc[r * 5 + c] += d.x * wv[c].x + d.y * wv[c].y
                                            + d.z * wv[c].z + d.w * wv[c].w;
                    }
                }
                #pragma unroll
                for (int rc = 0; rc < 20; ++rc) {
                    float v = acc[rc];
                    #pragma unroll
                    for (int off = 16; off; off >>= 1)
                        v += __shfl_xor_sync(0xffffffffu, v, off);
                    if (lane == 0) {
                        const int r = rc / 5, c = rc % 5;
                        const int o = os * 5 + c, k = k0 + r;
                        if (o < 8)       s_G[o * 2048 + k] = v;
                        else if (o < 16) s_G[(o - 8) * 2048 + 1024 + k] = v;
                        else             s_E[(o - 16) * 1024 + k] = v;
                    }
                }
            }
        }
    }
    __syncthreads();

    // ===== stage 4: D2 own cols -> s_w2 (overwrite W1 temp) =====
    for (int idx = t; idx < 8 * 1024; idx += NTHR) {
        int il = idx & 7, kk = idx >> 3;
        s_w2[il * 1024 + kk] = __ldg(D2 + (size_t)kk * DIM + bid * 8 + il);
    }
    bar_arrive(BAR1);

    // ================= step loop (1 exposed barrier/step) =================
    for (int s = 0; s < NSTEPS; ++s) {
        const int p = s & 1;
        const unsigned tgt = (unsigned)(s + 1) * (NBLK / NGRP);
        const float* cm1 = s_c + (1 - p) * 128;
        const float* h1row = g_h1[p] + b * DIM;

        bar_wait(BAR1, tgt);
        if (bid < NREP && t >= 128 && t < 256) g_coefR[1 - p][bid][t - 128] = 0.f;

        // ---- segA: z update via E matvec -> gelu -> coef partials ----
        {
            ull accE[4] = {0ull, 0ull, 0ull, 0ull};
            #pragma unroll
            for (int q = 0; q < 4; ++q) {
                const int k = q * 256 + kg * 4;
                ulonglong2 a = *reinterpret_cast<const ulonglong2*>(h1row + k);
                #pragma unroll
                for (int ml = 0; ml < 4; ++ml) {
                    ulonglong2 w = *reinterpret_cast<const ulonglong2*>(s_E + ml * 1024 + k);
                    fma2(accE[ml], w.x, a.x);
                    fma2(accE[ml], w.y, a.y);
                }
            }
            reduceN<4>(s_red, accE, t);
        }
        __syncthreads();
        if (t < 32) {
            int bb = t >> 2, ml = t & 3;
            float sum = 0.f;
            #pragma unroll
            for (int w = 0; w < 16; ++w) sum += s_red[(w * 8 + bb) * 4 + ml];
            float zc = 0.f;
            #pragma unroll
            for (int c = 0; c < NB; ++c) zc += cm1[bb * NB + c] * s_basW1[c * 4 + ml];
            float z = s_z[t] + sum + 0.1f * zc + s_bb[36 + ml];
            s_z[t] = z;
            s_g8[t] = 0.5f * z * (1.0f + erff(z * 0.70710678118654752f));
        }
        __syncthreads();
        if (t < 128) {
            int bb = t >> 4, cc = t & 15;
            float a = 0.f;
            #pragma unroll
            for (int ml = 0; ml < 4; ++ml) a += s_g8[bb * 4 + ml] * s_wc2[ml * NB + cc];
            atomicAdd(&g_coefR[p][bid & (NREP - 1)][t], a);
        }
        bar_arrive(BAR2);

        // ---- segB: Gt/Gb/D2own matvecs over h1_s (hide BAR2 RT) ----
        {
            ull accA[8];
            #pragma unroll
            for (int o = 0; o < 8; ++o) accA[o] = 0ull;
            acc8(accA, h1row, s_G, 2048, 0, kg);
            reduceN<8>(s_red + 512, accA, t);
        }
        {
            ull accB[8];
            #pragma unroll
            for (int o = 0; o < 8; ++o) accB[o] = 0ull;
            acc8(accB, h1row, s_G, 2048, 1024, kg);
            reduceN<8>(s_red + 1536, accB, t);
        }
        {
            ull accC[8];
            #pragma unroll
            for (int o = 0; o < 8; ++o) accC[o] = 0ull;
            acc8(accC, h1row, s_w2, 1024, 0, kg);
            reduceN<8>(s_red + 2560, accC, t);
        }
        bar_wait(BAR2, tgt);
        if (t < 128) {
            float crep = 0.f;
            #pragma unroll
            for (int r = 0; r < NREP; ++r) crep += g_coefR[p][r][t];
            s_c[p * 128 + t] = crep + s_bb[20 + (t & 15)];
        }
        __syncthreads();

        // ---- tails: wp/vp/nown updates + h1_{s+1} ----
        if (t < 64) {
            const int bb = t >> 3, jl = t & 7;
            float gt = 0.f, gb = 0.f, d2 = 0.f;
            #pragma unroll
            for (int w = 0; w < 16; ++w) {
                gt += s_red[512  + (w * 8 + bb) * 8 + jl];
                gb += s_red[1536 + (w * 8 + bb) * 8 + jl];
                d2 += s_red[2560 + (w * 8 + bb) * 8 + jl];
            }
            const float* cs = s_c + p * 128;
            float cdT = 0.f, cdB = 0.f, csT = 0.f, cbas = 0.f;
            #pragma unroll
            for (int c = 0; c < NB; ++c) {
                float c1 = cm1[bb * NB + c];
                cdT  += c1 * s_bd1t[c * 8 + jl];
                cdB  += c1 * s_bd1b[c * 8 + jl];
                csT  += cs[bb * NB + c] * s_bd1t[c * 8 + jl];
                cbas += c1 * s_bas[c * 8 + jl];
            }
            float wp_new = s_wp[t] + gt + s_bb[40 + jl] + 0.1f * cdT;
            float vp_old = s_vp[t];
            float h1v = tanhf(wp_new + vp_old + s_bb[jl] + 0.1f * (csT + cdB));
            s_wp[t] = wp_new;
            s_vp[t] = vp_old + gb + s_bb[48 + jl] + 0.1f * cdB;
            s_nown[t] = s_nown[t] + d2 + s_bb[8 + jl] + 0.1f * cbas;
            g_h1[1 - p][bb * DIM + bid * 8 + jl] = h1v;
        }
        bar_arrive(BAR1);

        // ---- output row SEQ+s (after arrive; off critical path) ----
        if (t >= 64 && t < 80) {
            int tt = t - 64, bb = tt >> 1, hf = tt & 1;
            int c0 = bid * 8 + hf * 4;
            const float* cs = s_c + p * 128;
            float o[4];
            #pragma unroll
            for (int xi = 0; xi < 4; ++xi) {
                float corr = 0.f;
                #pragma unroll
                for (int c = 0; c < NB; ++c)
                    corr += cs[bb * NB + c] * s_bas[c * 8 + hf * 4 + xi];
                o[xi] = s_nown[bb * 8 + hf * 4 + xi] + 0.1f * corr;
            }
            *reinterpret_cast<float4*>(out + ((size_t)bb * TLEN + SEQ + s) * DIM + c0) =
                make_float4(o[0], o[1], o[2], o[3]);
        }
    }

    // ================= done barrier + counter reset (replay safety) =================
    __syncthreads();
    if (t == 0) {
        asm volatile("red.release.gpu.global.add.u32 [%0], %1;"
                     :: "l"(&g_done), "r"(1u) : "memory");
        if (bid == 0) {
            unsigned v;
            do {
                asm volatile("ld.acquire.gpu.global.u32 %0, [%1];"
                             : "=r"(v) : "l"(&g_done) : "memory");
            } while (v < (unsigned)NBLK);
            for (int i = 0; i < 2 * NGRP; ++i) g_bcnt[i * GPAD] = 0;
            g_done = 0;
        }
    }
}

// ---------------- launch ----------------
extern "C" void kernel_launch(void* const* d_in, const int* in_sizes, int n_in,
                              void* d_out, int out_size) {
    const float* x     = (const float*)d_in[0];
    const float* basis = (const float*)d_in[1];
    const float* W1    = (const float*)d_in[2];
    const float* b1    = (const float*)d_in[3];
    const float* W2    = (const float*)d_in[4];
    const float* b2v   = (const float*)d_in[5];
    const float* D1    = (const float*)d_in[6];
    const float* bD1   = (const float*)d_in[7];
    const float* D2    = (const float*)d_in[8];
    const float* bD2   = (const float*)d_in[9];
    float* out = (float*)d_out;

    copy_kernel<<<4096, 1024>>>((const float4*)x, (float4*)out);

    size_t smem_bytes = (size_t)SMEM_FLOATS * sizeof(float);   // ~194 KB
    cudaFuncSetAttribute(extrap_kernel, cudaFuncAttributeMaxDynamicSharedMemorySize,
                         (int)smem_bytes);
    extrap_kernel<<<NBLK, NTHR, smem_bytes>>>(x, basis, W1, b1, W2, b2v,
                                              D1, bD1, D2, bD2, out);
}